// round 7
// baseline (speedup 1.0000x reference)
#include <cuda_runtime.h>
#include <cuda_bf16.h>
#include <cstdint>

// VQ-VAE bottleneck — legacy-HMMA (mma.sync bf16) distance GEMM + exact rescore.
// (tcgen05 unavailable: harness compiles baseline compute_103 PTX.)
//
// Per CTA: 128 positions x 512 codewords.
//   D[m,k] = (-2 z_m) . e_k  via 3 split-bf16 passes (a1e1 + a1e2 + a2e1), f32 accum.
//   s_k = D + ||e_k||^2 (row-constant Z dropped). gap >= MARGIN -> approx argmin
//   == reference argmin (error bound). gap < MARGIN -> rescore ALL 512 k with the
//   bit-exact fp32 emulation d = RN(RN(Z+B_k) - 2*seqFMA(z,e_k)), (d,k)-lex min
//   (validated rounds 2-5, rel_err ~2e-7).
// Output: straight-through RN(x + RN(q-x)); loss = RN(L + RN(0.25L)), L = SSE/N.

#define CDIM    64
#define KCODES  512
#define HW      4096
#define NELEM   8388608
#define THREADS 256
#define P_CTA   128
#define GRIDSZ  1024
#define MARGIN  6e-5f
#define RS      72            // tile row stride in elements (144B): conflict-free LDSM

typedef unsigned long long u64;
typedef unsigned int u32;

__device__ float g_loss_sum;
__device__ u32   g_done;

// smem layout (bytes)
#define OFF_A(h) ((h) * 18432)            // 2 x 128*144
#define OFF_B(h) (36864 + (h) * 73728)    // 2 x 512*144
#define OFF_ZF   184320                   // f32 z tile [c][128], 32 KB
#define OFF_ZS   217088                   // Z per row, 128 f32
#define OFF_E2   217600                   // ||e_k||^2, 512 f32
#define OFF_KB   219648                   // kbest, 128 u32
#define OFF_FL   220160                   // flags, 128 u32
#define SMEM_SZ  220672

__device__ __forceinline__ u32 smem_u32(const void* p) {
    u32 a; asm("{ .reg .u64 t; cvta.to.shared.u64 t, %1; cvt.u32.u64 %0, t; }" : "=r"(a) : "l"(p));
    return a;
}
__device__ __forceinline__ void ldsm4(u32 addr, u32& r0, u32& r1, u32& r2, u32& r3) {
    asm volatile("ldmatrix.sync.aligned.m8n8.x4.shared.b16 {%0,%1,%2,%3}, [%4];"
                 : "=r"(r0), "=r"(r1), "=r"(r2), "=r"(r3) : "r"(addr));
}
__device__ __forceinline__ void mma_bf16(float* d, const u32* a, u32 b0, u32 b1) {
    asm volatile("mma.sync.aligned.m16n8k16.row.col.f32.bf16.bf16.f32 "
                 "{%0,%1,%2,%3}, {%4,%5,%6,%7}, {%8,%9}, {%0,%1,%2,%3};"
                 : "+f"(d[0]), "+f"(d[1]), "+f"(d[2]), "+f"(d[3])
                 : "r"(a[0]), "r"(a[1]), "r"(a[2]), "r"(a[3]), "r"(b0), "r"(b1));
}
__device__ __forceinline__ u32 ord(u32 fb) {      // float bits -> monotone unsigned
    return fb ^ ((fb & 0x80000000u) ? 0xFFFFFFFFu : 0x80000000u);
}
__device__ __forceinline__ float dec(u32 o) {     // inverse of ord
    u32 fb = (o & 0x80000000u) ? (o ^ 0x80000000u) : ~o;
    return __uint_as_float(fb);
}
__device__ __forceinline__ void upd(u64& m1, u64& m2, u64 key) {
    if (key < m1) { m2 = m1; m1 = key; } else if (key < m2) { m2 = key; }
}
__device__ __forceinline__ void merge2(u64& m1, u64& m2, u64 q1, u64 q2) {
    u64 lo = m1 < q1 ? m1 : q1;
    u64 hi = m1 < q1 ? q1 : m1;
    u64 s2 = m2 < q2 ? m2 : q2;
    m1 = lo; m2 = hi < s2 ? hi : s2;
}

extern __shared__ char smc[];

__global__ __launch_bounds__(THREADS, 1)
void vq_main_kernel(const float* __restrict__ x,
                    const float* __restrict__ cb,
                    float* __restrict__ out,
                    int loss_idx) {
    const u32 sb   = smem_u32(smc);
    const int tid  = threadIdx.x;
    const int w    = tid >> 5;
    const int lane = tid & 31;

    float* zf  = (float*)(smc + OFF_ZF);
    float* Zs  = (float*)(smc + OFF_ZS);
    float* e2s = (float*)(smc + OFF_E2);
    u32*   kbs = (u32*)(smc + OFF_KB);
    u32*   fls = (u32*)(smc + OFF_FL);

    const int b   = blockIdx.x >> 5;
    const int hw0 = (blockIdx.x & 31) * P_CTA;
    const float* xrow = x + (size_t)b * CDIM * HW + hw0;

    // ---- x tile -> zf32 + split-bf16 A tiles (a = -2z), [m][c] rows of 144B ----
    for (int idx = tid; idx < CDIM * P_CTA; idx += THREADS) {
        int c = idx >> 7, p = idx & 127;
        float v = xrow[(size_t)c * HW + p];
        zf[c * P_CTA + p] = v;
        float a = -2.0f * v;                              // exact
        __nv_bfloat16 a1 = __float2bfloat16_rn(a);
        __nv_bfloat16 a2 = __float2bfloat16_rn(__fadd_rn(a, -__bfloat162float(a1)));
        u32 o = (u32)(p * RS + c) * 2;
        *(__nv_bfloat16*)(smc + OFF_A(0) + o) = a1;
        *(__nv_bfloat16*)(smc + OFF_A(1) + o) = a2;
    }
    // ---- codebook -> split-bf16 B tiles, [k][c] rows of 144B ----
    for (int idx = tid; idx < KCODES * CDIM; idx += THREADS) {
        int k = idx >> 6, c = idx & 63;
        float v = cb[idx];
        __nv_bfloat16 e1 = __float2bfloat16_rn(v);
        __nv_bfloat16 e2 = __float2bfloat16_rn(__fadd_rn(v, -__bfloat162float(e1)));
        u32 o = (u32)(k * RS + c) * 2;
        *(__nv_bfloat16*)(smc + OFF_B(0) + o) = e1;
        *(__nv_bfloat16*)(smc + OFF_B(1) + o) = e2;
    }
    // ---- ||e_k||^2, reference order ----
    for (int k = tid; k < KCODES; k += THREADS) {
        float s = 0.0f;
        const float* ek = cb + k * CDIM;
        #pragma unroll
        for (int c = 0; c < CDIM; c++) s = __fadd_rn(s, __fmul_rn(ek[c], ek[c]));
        e2s[k] = s;
    }
    __syncthreads();
    // ---- Z per row, reference order ----
    if (tid < P_CTA) {
        float s = 0.0f;
        #pragma unroll
        for (int c = 0; c < CDIM; c++) {
            float zv = zf[c * P_CTA + tid];
            s = __fadd_rn(s, __fmul_rn(zv, zv));
        }
        Zs[tid] = s;
    }
    __syncthreads();

    // ---- HMMA mainloop: warp w owns rows [16w, 16w+16) ----
    const int m_base = w * 16;
    const int g      = lane >> 2;        // 0..7
    const int t4     = lane & 3;         // 0..3

    // A fragments cached: both split halves, 4 k-steps
    u32 afr[2][4][4];
    {
        int a_r  = lane & 15;
        int a_c8 = (lane >> 4) << 3;
        #pragma unroll
        for (int h = 0; h < 2; h++)
            #pragma unroll
            for (int ks = 0; ks < 4; ks++) {
                u32 ad = sb + OFF_A(h) + (u32)((m_base + a_r) * RS + ks * 16 + a_c8) * 2;
                ldsm4(ad, afr[h][ks][0], afr[h][ks][1], afr[h][ks][2], afr[h][ks][3]);
            }
    }

    const int b_r = (lane & 7) + ((lane >> 4) << 3);
    const int b_c = ((lane >> 3) & 1) << 3;

    u64 mA1 = ~0ull, mA2 = ~0ull;        // row m_base+g
    u64 mB1 = ~0ull, mB2 = ~0ull;        // row m_base+g+8

    #pragma unroll 1
    for (int nc = 0; nc < 8; nc++) {     // 64 codewords per chunk
        float acc[8][4];
        #pragma unroll
        for (int i = 0; i < 8; i++)
            #pragma unroll
            for (int j = 0; j < 4; j++) acc[i][j] = 0.0f;

        #pragma unroll
        for (int ps = 0; ps < 3; ps++) { // (a1,e1), (a1,e2), (a2,e1)
            const int ha = (ps == 2) ? 1 : 0;
            const int hb = (ps == 1) ? 1 : 0;
            const u32 bbase = sb + OFF_B(hb);
            #pragma unroll
            for (int ks = 0; ks < 4; ks++) {
                #pragma unroll
                for (int pr = 0; pr < 4; pr++) {   // 2 ntiles per ldmatrix.x4
                    u32 ad = bbase + (u32)((nc * 64 + pr * 16 + b_r) * RS
                                           + ks * 16 + b_c) * 2;
                    u32 b0, b1, b2, b3;
                    ldsm4(ad, b0, b1, b2, b3);
                    mma_bf16(acc[2 * pr],     afr[ha][ks], b0, b1);
                    mma_bf16(acc[2 * pr + 1], afr[ha][ks], b2, b3);
                }
            }
        }
        // epilogue: s = D + e2, fold into running (min1,min2)
        #pragma unroll
        for (int nt = 0; nt < 8; nt++) {
            int col0 = nc * 64 + nt * 8 + 2 * t4;
            float e20 = e2s[col0], e21 = e2s[col0 + 1];
            float s0 = acc[nt][0] + e20;
            float s1 = acc[nt][1] + e21;
            float s2 = acc[nt][2] + e20;
            float s3 = acc[nt][3] + e21;
            upd(mA1, mA2, ((u64)ord(__float_as_uint(s0)) << 32) | (u32)col0);
            upd(mA1, mA2, ((u64)ord(__float_as_uint(s1)) << 32) | (u32)(col0 + 1));
            upd(mB1, mB2, ((u64)ord(__float_as_uint(s2)) << 32) | (u32)col0);
            upd(mB1, mB2, ((u64)ord(__float_as_uint(s3)) << 32) | (u32)(col0 + 1));
        }
    }

    // quad reduce (lanes g*4+t, t=0..3)
    #pragma unroll
    for (int o = 1; o <= 2; o <<= 1) {
        merge2(mA1, mA2, __shfl_xor_sync(0xffffffffu, mA1, o),
                         __shfl_xor_sync(0xffffffffu, mA2, o));
        merge2(mB1, mB2, __shfl_xor_sync(0xffffffffu, mB1, o),
                         __shfl_xor_sync(0xffffffffu, mB2, o));
    }
    if (t4 == 0) {
        int r0 = m_base + g, r1 = m_base + g + 8;
        kbs[r0] = (u32)(mA1 & 0x1FFu);
        kbs[r1] = (u32)(mB1 & 0x1FFu);
        fls[r0] = (dec((u32)(mA2 >> 32)) - dec((u32)(mA1 >> 32))) < MARGIN;
        fls[r1] = (dec((u32)(mB2 >> 32)) - dec((u32)(mB1 >> 32))) < MARGIN;
    }
    __syncwarp();

    // ---- exact rescore of flagged rows (whole warp per row, all 512 k) ----
    for (int r = 0; r < 16; r++) {
        int row = m_base + r;
        if (!fls[row]) continue;
        float Zp = Zs[row];
        u64 best = ~0ull;
        #pragma unroll 1
        for (int k = lane; k < KCODES; k += 32) {
            const float* ek = cb + k * CDIM;
            float mz = 0.0f;
            #pragma unroll
            for (int c = 0; c < CDIM; c++)
                mz = __fmaf_rn(zf[c * P_CTA + row], __ldg(ek + c), mz); // c asc.
            float tt = __fadd_rn(Zp, e2s[k]);
            float d  = __fadd_rn(tt, -2.0f * mz);
            u64 key = ((u64)__float_as_uint(d) << 32) | (u32)k;  // d > 0
            if (key < best) best = key;
        }
        #pragma unroll
        for (int o = 16; o; o >>= 1) {
            u64 v = __shfl_xor_sync(0xffffffffu, best, o);
            if (v < best) best = v;
        }
        if (lane == 0) kbs[row] = (u32)(best & 0x1FFu);
    }
    __syncthreads();

    // ---- writeback: straight-through RN(x + RN(q-x)) + SSE ----
    {
        int p = tid & 127, ch = tid >> 7;
        u32 kb = kbs[p];
        const float* qk = cb + (size_t)kb * CDIM;
        float* op = out + (size_t)b * CDIM * HW + hw0 + p;
        float sse = 0.0f;
        #pragma unroll 8
        for (int c = ch * 32; c < ch * 32 + 32; c++) {
            float zv   = zf[c * P_CTA + p];
            float qv   = __ldg(qk + c);
            float diff = __fadd_rn(qv, -zv);
            op[(size_t)c * HW] = __fadd_rn(zv, diff);
            sse = __fadd_rn(sse, __fmul_rn(diff, diff));
        }
        #pragma unroll
        for (int o = 16; o; o >>= 1) sse += __shfl_xor_sync(0xffffffffu, sse, o);
        if (lane == 0) atomicAdd(&g_loss_sum, sse);
    }

    // ---- fused finalize, reset for next graph replay ----
    __syncthreads();
    if (tid == 0) {
        __threadfence();
        u32 done = atomicAdd(&g_done, 1u);
        if (done == gridDim.x - 1) {
            float L = atomicAdd(&g_loss_sum, 0.0f) * (1.0f / (float)NELEM);
            if (loss_idx >= 0)
                out[loss_idx] = __fadd_rn(L, 0.25f * L);
            g_loss_sum = 0.0f;
            g_done     = 0u;
            __threadfence();
        }
    }
}

extern "C" void kernel_launch(void* const* d_in, const int* in_sizes, int n_in,
                              void* d_out, int out_size) {
    const float* x   = (const float*)d_in[0];
    const float* cb  = (const float*)d_in[1];
    float*       out = (float*)d_out;

    cudaFuncSetAttribute(vq_main_kernel,
                         cudaFuncAttributeMaxDynamicSharedMemorySize, SMEM_SZ);
    int loss_idx = (out_size > NELEM) ? (out_size - 1) : -1;
    vq_main_kernel<<<GRIDSZ, THREADS, SMEM_SZ>>>(x, cb, out, loss_idx);
}